// round 9
// baseline (speedup 1.0000x reference)
#include <cuda_runtime.h>
#include <cuda_fp16.h>
#include <cstdint>

// Problem constants (fixed shapes)
#define BATCH 32768
#define DIM   1024
#define NH    8
#define HDIM  128
#define HID   1024
#define KCONV 4
#define EPS_  1e-6f
#define CAP_  15.0f

// ---------------- scratch (static device globals; no allocation) -------------
__device__ __half g_xconv[(size_t)BATCH * DIM];  // SiLU(conv gemm), fp16
__device__ float g_z[(size_t)BATCH * DIM];       // z projection, fp32
__device__ float g_pre[(size_t)BATCH * NH * 3];  // i_t, f_t, o_t per (b,h)
__device__ __half g_in[(size_t)BATCH * DIM];     // inputs, fp16
__device__ __half g_hn[(size_t)BATCH * DIM];     // h_norm, fp16
__device__ __half g_wz[(size_t)2 * DIM * DIM];   // [w1 | z_w] packed, fp16
__device__ __half g_ow[(size_t)DIM * DIM];

// ---------------- helpers -----------------------------------------------------
__device__ __forceinline__ uint32_t smem_u32(const void* p) {
    uint32_t a;
    asm("{ .reg .u64 t; cvta.to.shared.u64 t, %1; cvt.u32.u64 %0, t; }"
        : "=r"(a) : "l"(p));
    return a;
}

__device__ __forceinline__ void cp_async16(uint32_t dst, const void* src) {
    asm volatile("cp.async.cg.shared.global [%0], [%1], 16;"
                 :: "r"(dst), "l"(src) : "memory");
}
#define CP_COMMIT() asm volatile("cp.async.commit_group;" ::: "memory")
#define CP_WAIT(N)  asm volatile("cp.async.wait_group %0;" :: "n"(N) : "memory")

#define LDSM_X4(r0, r1, r2, r3, addr) \
    asm volatile("ldmatrix.sync.aligned.m8n8.x4.shared.b16 {%0,%1,%2,%3}, [%4];" \
                 : "=r"(r0), "=r"(r1), "=r"(r2), "=r"(r3) : "r"(addr))

#define MMA16816(d, a, b0v, b1v) \
    asm volatile("mma.sync.aligned.m16n8k16.row.col.f32.f16.f16.f32 " \
                 "{%0,%1,%2,%3}, {%4,%5,%6,%7}, {%8,%9}, {%0,%1,%2,%3};" \
                 : "+f"((d)[0]), "+f"((d)[1]), "+f"((d)[2]), "+f"((d)[3]) \
                 : "r"((a)[0]), "r"((a)[1]), "r"((a)[2]), "r"((a)[3]), \
                   "r"(b0v), "r"(b1v))

// ---------------- conversion kernels -----------------------------------------
// fp32 -> fp16
__global__ __launch_bounds__(256)
void cvt_h_kernel(const float* __restrict__ src, __half* __restrict__ dst, int n4) {
    int i = blockIdx.x * blockDim.x + threadIdx.x;
    if (i >= n4) return;
    float4 v = ((const float4*)src)[i];
    __half2 a = {__float2half(v.x), __float2half(v.y)};
    __half2 b = {__float2half(v.z), __float2half(v.w)};
    uint2 p = {*(uint32_t*)&a, *(uint32_t*)&b};
    ((uint2*)dst)[i] = p;
}

// pack conv tap K-1 -> fp16 (into first half of g_wz)
__global__ __launch_bounds__(256)
void pack_w1_kernel(const float* __restrict__ conv_w) {
    int idx = blockIdx.x * blockDim.x + threadIdx.x;
    if (idx < DIM * DIM)
        g_wz[idx] = __float2half(conv_w[(size_t)idx * KCONV + (KCONV - 1)]);
}

// ---------------- fp16 MMA GEMM: C[m][n] = sum_k A[m][k]*W[n][k] -------------
// CTA tile 256x128, BK=32, 256 threads (8 warps, each 64x64).
// 3-stage cp.async pipeline, one __syncthreads per chunk.
#define GK      1024
#define BKC     32
#define NCHUNK  (GK / BKC)          // 32
#define NSTAGE  3
#define RSB     80                  // padded smem row stride (64B data + 16B pad)
#define TILE_A_SB (256 * RSB)       // 20480 B
#define TILE_B_SB (128 * RSB)       // 10240 B
#define STAGE_SB (TILE_A_SB + TILE_B_SB)  // 30720 B
#define GEMM_SMEM (NSTAGE * STAGE_SB)     // 92160 B

// EPI: 0 = plain fp32 C store (out GEMM, N=1024)
//      1 = fused input GEMM (N=2048): bn<1024 -> bias+SiLU -> half to Cx;
//                                     bn>=1024 -> fp32 to Cz
template <int EPI>
__global__ __launch_bounds__(256, 1)
void mma_gemm(const __half* __restrict__ A, const __half* __restrict__ B,
              const float* __restrict__ bias, float* __restrict__ C,
              __half* __restrict__ Cx) {
    extern __shared__ __align__(128) char dsm[];

    const int tid  = threadIdx.x;
    const int wid  = tid >> 5;
    const int lane = tid & 31;
    const int wm   = wid & 3;      // 0..3 -> row block of 64
    const int wn   = wid >> 2;     // 0..1 -> col block of 64
    const int bm = blockIdx.y * 256;
    const int bn = blockIdx.x * 128;

    const uint32_t sbase = smem_u32(dsm);

    const __half* srcA = A + (size_t)bm * GK;
    const __half* srcB = B + (size_t)bn * GK;

    // stage loader: A 256 rows + B 128 rows, 32 fp16 (64B) each; 16B per cp.async
    // 1536 chunks total -> 6 per thread
    auto load_stage = [&](int stage, int k0) {
#pragma unroll
        for (int i = 0; i < 6; i++) {
            int id = tid + i * 256;        // 0..1535
            uint32_t d;
            const void* g;
            if (id < 1024) {               // A part: rows 0..255
                int r  = id >> 2;
                int cq = id & 3;
                g = srcA + (size_t)r * GK + k0 + cq * 8;
                d = sbase + stage * STAGE_SB + r * RSB + cq * 16;
            } else {                       // B part: rows 0..127
                int id2 = id - 1024;
                int r  = id2 >> 2;
                int cq = id2 & 3;
                g = srcB + (size_t)r * GK + k0 + cq * 8;
                d = sbase + stage * STAGE_SB + TILE_A_SB + r * RSB + cq * 16;
            }
            cp_async16(d, g);
        }
        CP_COMMIT();
    };

    float acc[4][8][4];
#pragma unroll
    for (int a = 0; a < 4; a++)
#pragma unroll
        for (int b = 0; b < 8; b++)
#pragma unroll
            for (int q = 0; q < 4; q++) acc[a][b][q] = 0.f;

    // prologue: stages 0, 1
    load_stage(0, 0);
    load_stage(1, BKC);

    // fragment address offsets (within a tile)
    const int a_row = wm * 64 + (lane & 7) + ((lane >> 3) & 1) * 8;
    const int a_kof = (lane >> 4) * 8;
    const int b_row = wn * 64 + ((lane >> 4) * 8) + (lane & 7);
    const int b_kof = ((lane >> 3) & 1) * 8;

    int cur = 0, nxt = 2;                       // stage indices mod 3
    for (int ch = 0; ch < NCHUNK; ch++) {
        if (ch + 1 < NCHUNK) { CP_WAIT(NSTAGE - 2); } else { CP_WAIT(0); }
        __syncthreads();                        // everyone's done + buf free
        if (ch + 2 < NCHUNK) {
            load_stage(nxt, (ch + 2) * BKC);    // safe: old readers finished
        }

        const uint32_t st  = sbase + cur * STAGE_SB;
        const uint32_t t_a = st;
        const uint32_t t_b = st + TILE_A_SB;

#pragma unroll
        for (int ks = 0; ks < 2; ks++) {
            const int kq = ks * 16;
            uint32_t aa[4][4], bb[4][4];

#pragma unroll
            for (int mi = 0; mi < 4; mi++) {
                uint32_t ad = t_a + (a_row + mi * 16) * RSB + (kq + a_kof) * 2;
                LDSM_X4(aa[mi][0], aa[mi][1], aa[mi][2], aa[mi][3], ad);
            }
#pragma unroll
            for (int ni = 0; ni < 4; ni++) {
                uint32_t bd = t_b + (b_row + ni * 16) * RSB + (kq + b_kof) * 2;
                LDSM_X4(bb[ni][0], bb[ni][1], bb[ni][2], bb[ni][3], bd);
            }
#pragma unroll
            for (int mi = 0; mi < 4; mi++)
#pragma unroll
                for (int ni = 0; ni < 4; ni++) {
                    MMA16816(acc[mi][2 * ni],     aa[mi], bb[ni][0], bb[ni][1]);
                    MMA16816(acc[mi][2 * ni + 1], aa[mi], bb[ni][2], bb[ni][3]);
                }
        }
        cur = (cur + 1 == NSTAGE) ? 0 : cur + 1;
        nxt = (nxt + 1 == NSTAGE) ? 0 : nxt + 1;
    }

    // epilogue
#pragma unroll
    for (int mi = 0; mi < 4; mi++) {
#pragma unroll
        for (int h2 = 0; h2 < 2; h2++) {
            int row = bm + wm * 64 + mi * 16 + (lane >> 2) + h2 * 8;
#pragma unroll
            for (int ng = 0; ng < 8; ng++) {
                int col = bn + wn * 64 + ng * 8 + (lane & 3) * 2;
                float x0 = acc[mi][ng][h2 * 2];
                float x1 = acc[mi][ng][h2 * 2 + 1];
                if (EPI == 1) {
                    if (bn < DIM) {
                        // x_conv path: bias + SiLU -> fp16
                        x0 += bias[col];
                        x1 += bias[col + 1];
                        x0 = x0 / (1.f + __expf(-x0));
                        x1 = x1 / (1.f + __expf(-x1));
                        __half2 hv = {__float2half(x0), __float2half(x1)};
                        *(__half2*)(Cx + (size_t)row * DIM + col) = hv;
                    } else {
                        float2 v = {x0, x1};
                        *(float2*)(C + (size_t)row * DIM + (col - DIM)) = v;
                    }
                } else {
                    float2 v = {x0, x1};
                    *(float2*)(C + (size_t)row * DIM + col) = v;
                }
            }
        }
    }
}

// ---------------- gate pre-activations (weights cached in smem) --------------
__device__ __forceinline__ float warp_sum(float v) {
#pragma unroll
    for (int o = 16; o; o >>= 1) v += __shfl_xor_sync(0xffffffffu, v, o);
    return v;
}

__device__ __forceinline__ float softcap(float x) {
    return CAP_ * tanhf(x * (1.0f / CAP_));
}

#define PRE_ROWS 32
#define PRE_SMEM ((3 * NH * DIM + 2 * DIM) * 4)   // 106496 B

__global__ __launch_bounds__(256)
void preact_kernel(const float* __restrict__ inputs,
                   const float* __restrict__ i_w, const float* __restrict__ i_b,
                   const float* __restrict__ f_w, const float* __restrict__ f_b,
                   const float* __restrict__ o_w, const float* __restrict__ o_b) {
    extern __shared__ __align__(16) float sw[];
    float* s_iw = sw;                     // [NH*DIM]
    float* s_fw = s_iw + NH * DIM;
    float* s_ow = s_fw + NH * DIM;
    float* s_xc = s_ow + NH * DIM;        // [DIM]
    float* s_xi = s_xc + DIM;             // [DIM]

    const int tid = threadIdx.x;
    const int h = tid >> 5;
    const int lane = tid & 31;

    // cache all gate weights (96 KB) once per block
#pragma unroll
    for (int i = 0; i < 8; i++) {
        int idx = tid + i * 256;          // over NH*DIM/4 = 2048 float4
        ((float4*)s_iw)[idx] = ((const float4*)i_w)[idx];
        ((float4*)s_fw)[idx] = ((const float4*)f_w)[idx];
        ((float4*)s_ow)[idx] = ((const float4*)o_w)[idx];
    }
    __syncthreads();

    const float ib = i_b[h], fb = f_b[h], ob = o_b[h];
    const int row0 = blockIdx.x * PRE_ROWS;

    for (int r = 0; r < PRE_ROWS; r++) {
        const int row = row0 + r;
        // cooperative loads: xconv fp16 (converted to fp32 smem), inputs fp32
        {
            int idx = tid;                // 256 threads
            uint2 hx = ((const uint2*)(g_xconv + (size_t)row * DIM))[idx];
            __half2 h0 = *(__half2*)&hx.x;
            __half2 h1 = *(__half2*)&hx.y;
            float2 f0 = __half22float2(h0);
            float2 f1 = __half22float2(h1);
            float4 xf = {f0.x, f0.y, f1.x, f1.y};
            ((float4*)s_xc)[idx] = xf;
            ((float4*)s_xi)[idx] = ((const float4*)(inputs + (size_t)row * DIM))[idx];
        }
        __syncthreads();

        float di = 0.f, df = 0.f, dq = 0.f;
        const float4* xc4 = (const float4*)s_xc;
        const float4* xi4 = (const float4*)s_xi;
        const float4* iw4 = (const float4*)(s_iw + h * DIM);
        const float4* fw4 = (const float4*)(s_fw + h * DIM);
        const float4* ow4 = (const float4*)(s_ow + h * DIM);
#pragma unroll
        for (int kk = 0; kk < 8; kk++) {
            int k4 = kk * 32 + lane;
            float4 xc = xc4[k4], xi = xi4[k4];
            float4 iw = iw4[k4], fw = fw4[k4], ow = ow4[k4];
            di = fmaf(xc.x, iw.x, di); di = fmaf(xc.y, iw.y, di);
            di = fmaf(xc.z, iw.z, di); di = fmaf(xc.w, iw.w, di);
            df = fmaf(xc.x, fw.x, df); df = fmaf(xc.y, fw.y, df);
            df = fmaf(xc.z, fw.z, df); df = fmaf(xc.w, fw.w, df);
            dq = fmaf(xi.x, ow.x, dq); dq = fmaf(xi.y, ow.y, dq);
            dq = fmaf(xi.z, ow.z, dq); dq = fmaf(xi.w, ow.w, dq);
        }
        di = warp_sum(di);
        df = warp_sum(df);
        dq = warp_sum(dq);
        if (lane == 0) {
            size_t p = ((size_t)row * NH + h) * 3;
            g_pre[p + 0] = softcap(di + ib);
            g_pre[p + 1] = softcap(df + fb);
            g_pre[p + 2] = dq + ob;
        }
        __syncthreads();
    }
}

// ---------------- elementwise gating + per-head layernorm --------------------
__global__ __launch_bounds__(256)
void gate_kernel(const float* __restrict__ c, const float* __restrict__ n,
                 const float* __restrict__ m,
                 const float* __restrict__ gn_w, const float* __restrict__ gn_b,
                 float* __restrict__ out_c, float* __restrict__ out_n,
                 float* __restrict__ out_m) {
    const int b = blockIdx.x;
    const int tid = threadIdx.x;
    const int h = tid >> 5;          // warp == head (NH==8 warps)
    const int lane = tid & 31;

    const size_t p = ((size_t)b * NH + h) * 3;
    const float i_t = g_pre[p + 0];
    const float f_t = g_pre[p + 1];
    const float o_t = g_pre[p + 2];

    float f_log = -log1pf(expf(-f_t));       // log(sigmoid(f_t))
    float mm    = m[(size_t)b * NH + h];
    float m_new = fmaxf(f_log + mm, i_t);
    float i_g   = expf(i_t - m_new);
    float f_g   = expf(f_log + mm - m_new);
    float o_g   = 1.f / (1.f + expf(-o_t));

    const size_t base = (size_t)b * HID + h * HDIM;
    const int e = lane * 4;                  // 4 contiguous elements per lane

    float4 cv = *(const float4*)(c + base + e);
    float4 nv = *(const float4*)(n + base + e);
    float4 zv = *(const float4*)(g_z + base + e);

    float4 cn, nn, hv;
    cn.x = fmaf(f_g, cv.x, i_g * zv.x); nn.x = fmaf(f_g, nv.x, i_g);
    cn.y = fmaf(f_g, cv.y, i_g * zv.y); nn.y = fmaf(f_g, nv.y, i_g);
    cn.z = fmaf(f_g, cv.z, i_g * zv.z); nn.z = fmaf(f_g, nv.z, i_g);
    cn.w = fmaf(f_g, cv.w, i_g * zv.w); nn.w = fmaf(f_g, nv.w, i_g);
    *(float4*)(out_c + base + e) = cn;
    *(float4*)(out_n + base + e) = nn;

    hv.x = o_g * cn.x / (nn.x + EPS_);
    hv.y = o_g * cn.y / (nn.y + EPS_);
    hv.z = o_g * cn.z / (nn.z + EPS_);
    hv.w = o_g * cn.w / (nn.w + EPS_);

    float sum   = hv.x + hv.y + hv.z + hv.w;
    float sumsq = fmaf(hv.x, hv.x, fmaf(hv.y, hv.y, fmaf(hv.z, hv.z, hv.w * hv.w)));
    sum   = warp_sum(sum);
    sumsq = warp_sum(sumsq);
    float mu   = sum * (1.0f / HDIM);
    float var  = sumsq * (1.0f / HDIM) - mu * mu;
    float rstd = rsqrtf(var + EPS_);

    float4 gw = *(const float4*)(gn_w + h * HDIM + e);
    float4 gb = *(const float4*)(gn_b + h * HDIM + e);
    float h0 = (hv.x - mu) * rstd * gw.x + gb.x;
    float h1 = (hv.y - mu) * rstd * gw.y + gb.y;
    float h2 = (hv.z - mu) * rstd * gw.z + gb.z;
    float h3 = (hv.w - mu) * rstd * gw.w + gb.w;
    __half2 p0 = {__float2half(h0), __float2half(h1)};
    __half2 p1 = {__float2half(h2), __float2half(h3)};
    uint2 hp = {*(uint32_t*)&p0, *(uint32_t*)&p1};
    *(uint2*)(g_hn + base + e) = hp;

    if (lane == 0) out_m[(size_t)b * NH + h] = m_new;
}

// ---------------- launch ------------------------------------------------------
extern "C" void kernel_launch(void* const* d_in, const int* in_sizes, int n_in,
                              void* d_out, int out_size) {
    const float* inputs = (const float*)d_in[0];
    const float* c      = (const float*)d_in[1];
    const float* n      = (const float*)d_in[2];
    const float* m      = (const float*)d_in[3];
    const float* conv_w = (const float*)d_in[4];
    const float* conv_b = (const float*)d_in[5];
    const float* z_w    = (const float*)d_in[6];
    const float* i_w    = (const float*)d_in[7];
    const float* i_b    = (const float*)d_in[8];
    const float* f_w    = (const float*)d_in[9];
    const float* f_b    = (const float*)d_in[10];
    const float* o_w    = (const float*)d_in[11];
    const float* o_b    = (const float*)d_in[12];
    const float* gn_w   = (const float*)d_in[13];
    const float* gn_b   = (const float*)d_in[14];
    const float* out_w  = (const float*)d_in[15];

    float* out   = (float*)d_out;                       // [B, D]
    float* out_c = out   + (size_t)BATCH * DIM;         // [B, NH, H]
    float* out_n = out_c + (size_t)BATCH * DIM;         // [B, NH, H]
    float* out_m = out_n + (size_t)BATCH * DIM;         // [B, NH]

    float *z_p;
    __half *xconv_p, *in_p, *hn_p, *wz_p, *ow_p;
    cudaGetSymbolAddress((void**)&xconv_p, g_xconv);
    cudaGetSymbolAddress((void**)&z_p, g_z);
    cudaGetSymbolAddress((void**)&in_p, g_in);
    cudaGetSymbolAddress((void**)&hn_p, g_hn);
    cudaGetSymbolAddress((void**)&wz_p, g_wz);
    cudaGetSymbolAddress((void**)&ow_p, g_ow);

    cudaFuncSetAttribute(mma_gemm<0>, cudaFuncAttributeMaxDynamicSharedMemorySize, GEMM_SMEM);
    cudaFuncSetAttribute(mma_gemm<1>, cudaFuncAttributeMaxDynamicSharedMemorySize, GEMM_SMEM);
    cudaFuncSetAttribute(preact_kernel, cudaFuncAttributeMaxDynamicSharedMemorySize, PRE_SMEM);

    // conversions
    {
        int n4 = (BATCH * DIM) / 4;
        cvt_h_kernel<<<n4 / 256, 256>>>(inputs, in_p, n4);
    }
    pack_w1_kernel<<<(DIM * DIM + 255) / 256, 256>>>(conv_w);
    {
        int n4 = (DIM * DIM) / 4;
        cvt_h_kernel<<<n4 / 256, 256>>>(z_w, wz_p + (size_t)DIM * DIM, n4);
        cvt_h_kernel<<<n4 / 256, 256>>>(out_w, ow_p, n4);
    }

    // fused input GEMM: [x_conv | z] = inputs @ [w1 | z_w]^T   (N = 2048)
    {
        dim3 g(2 * DIM / 128, BATCH / 256);   // (16, 128)
        mma_gemm<1><<<g, 256, GEMM_SMEM>>>(in_p, wz_p, conv_b, z_p, xconv_p);
    }
    // gate pre-activations (i_t, f_t, o_t)
    preact_kernel<<<BATCH / PRE_ROWS, 256, PRE_SMEM>>>(inputs, i_w, i_b, f_w, f_b, o_w, o_b);
    // elementwise gating + LN (emits h_norm as fp16)
    gate_kernel<<<BATCH, 256>>>(c, n, m, gn_w, gn_b, out_c, out_n, out_m);
    // out = h_norm @ out_w^T
    {
        dim3 g(DIM / 128, BATCH / 256);       // (8, 128)
        mma_gemm<0><<<g, 256, GEMM_SMEM>>>(hn_p, ow_p, nullptr, out, nullptr);
    }
}

// round 12
// speedup vs baseline: 1.1785x; 1.1785x over previous
#include <cuda_runtime.h>
#include <cuda_fp16.h>
#include <cstdint>

// Problem constants (fixed shapes)
#define BATCH 32768
#define DIM   1024
#define NH    8
#define HDIM  128
#define HID   1024
#define KCONV 4
#define EPS_  1e-6f
#define CAP_  15.0f

// ---------------- scratch (static device globals; no allocation) -------------
__device__ __half g_xconv[(size_t)BATCH * DIM];  // SiLU(conv gemm), fp16
__device__ float g_z[(size_t)BATCH * DIM];       // z projection, fp32
__device__ float g_pre[(size_t)BATCH * NH * 3];  // i_t, f_t, o_t per (b,h)
__device__ __half g_in[(size_t)BATCH * DIM];     // inputs, fp16
__device__ __half g_hn[(size_t)BATCH * DIM];     // h_norm, fp16
__device__ __half g_wz[(size_t)2 * DIM * DIM];   // [w1 | z_w] packed, fp16
__device__ __half g_ow[(size_t)DIM * DIM];

// ---------------- helpers -----------------------------------------------------
__device__ __forceinline__ uint32_t smem_u32(const void* p) {
    uint32_t a;
    asm("{ .reg .u64 t; cvta.to.shared.u64 t, %1; cvt.u32.u64 %0, t; }"
        : "=r"(a) : "l"(p));
    return a;
}

__device__ __forceinline__ void cp_async16(uint32_t dst, const void* src) {
    asm volatile("cp.async.cg.shared.global [%0], [%1], 16;"
                 :: "r"(dst), "l"(src) : "memory");
}
#define CP_COMMIT() asm volatile("cp.async.commit_group;" ::: "memory")
#define CP_WAIT(N)  asm volatile("cp.async.wait_group %0;" :: "n"(N) : "memory")

#define LDSM_X4(r0, r1, r2, r3, addr) \
    asm volatile("ldmatrix.sync.aligned.m8n8.x4.shared.b16 {%0,%1,%2,%3}, [%4];" \
                 : "=r"(r0), "=r"(r1), "=r"(r2), "=r"(r3) : "r"(addr))

#define MMA16816(d, a, b0v, b1v) \
    asm volatile("mma.sync.aligned.m16n8k16.row.col.f32.f16.f16.f32 " \
                 "{%0,%1,%2,%3}, {%4,%5,%6,%7}, {%8,%9}, {%0,%1,%2,%3};" \
                 : "+f"((d)[0]), "+f"((d)[1]), "+f"((d)[2]), "+f"((d)[3]) \
                 : "r"((a)[0]), "r"((a)[1]), "r"((a)[2]), "r"((a)[3]), \
                   "r"(b0v), "r"(b1v))

// ---------------- conversion kernels -----------------------------------------
// fp32 -> fp16
__global__ __launch_bounds__(256)
void cvt_h_kernel(const float* __restrict__ src, __half* __restrict__ dst, int n4) {
    int i = blockIdx.x * blockDim.x + threadIdx.x;
    if (i >= n4) return;
    float4 v = ((const float4*)src)[i];
    __half2 a = {__float2half(v.x), __float2half(v.y)};
    __half2 b = {__float2half(v.z), __float2half(v.w)};
    uint2 p = {*(uint32_t*)&a, *(uint32_t*)&b};
    ((uint2*)dst)[i] = p;
}

// pack conv tap K-1 -> fp16 (into first half of g_wz)
__global__ __launch_bounds__(256)
void pack_w1_kernel(const float* __restrict__ conv_w) {
    int idx = blockIdx.x * blockDim.x + threadIdx.x;
    if (idx < DIM * DIM)
        g_wz[idx] = __float2half(conv_w[(size_t)idx * KCONV + (KCONV - 1)]);
}

// ---------------- fp16 MMA GEMM: C[m][n] = sum_k A[m][k]*W[n][k] -------------
// CTA tile 128x128, BK=64, 256 threads (warps 4x2, each 32x64).
// 3-stage cp.async pipeline, one __syncthreads per chunk.
#define GK      1024
#define BKC     64
#define NCHUNK  (GK / BKC)          // 16
#define NSTAGE  3
#define RSB     144                 // padded smem row stride (128B data + 16B pad)
#define TILE_SB (128 * RSB)         // 18432 B per tile
#define STAGE_SB (2 * TILE_SB)      // A, B = 36864 B
#define GEMM_SMEM (NSTAGE * STAGE_SB) // 110592 B

// EPI: 0 = plain fp32 C store (out GEMM, N=1024)
//      1 = fused input GEMM (N=2048): bn<1024 -> bias+SiLU -> half to Cx;
//                                     bn>=1024 -> fp32 to Cz
template <int EPI>
__global__ __launch_bounds__(256, 2)
void mma_gemm(const __half* __restrict__ A, const __half* __restrict__ B,
              const float* __restrict__ bias, float* __restrict__ C,
              __half* __restrict__ Cx) {
    extern __shared__ __align__(128) char dsm[];

    const int tid  = threadIdx.x;
    const int wid  = tid >> 5;
    const int lane = tid & 31;
    const int wm   = wid & 3;      // 0..3 -> row block of 32
    const int wn   = wid >> 2;     // 0..1 -> col block of 64
    const int bm = blockIdx.y * 128;
    const int bn = blockIdx.x * 128;

    const uint32_t sbase = smem_u32(dsm);

    const __half* srcA = A + (size_t)bm * GK;
    const __half* srcB = B + (size_t)bn * GK;

    // stage loader: 2 tiles of 128 rows x 64 fp16 (128B); 16B per cp.async
    // 2048 chunks total -> 8 per thread
    auto load_stage = [&](int stage, int k0) {
#pragma unroll
        for (int i = 0; i < 8; i++) {
            int id = tid + i * 256;        // 0..2047
            int t  = id >> 10;             // tile (0=A, 1=B)
            int r  = (id >> 3) & 127;      // row
            int cq = id & 7;               // 16B chunk in row
            const __half* s = (t == 0) ? srcA : srcB;
            const void* g = s + (size_t)r * GK + k0 + cq * 8;
            uint32_t d = sbase + stage * STAGE_SB + t * TILE_SB + r * RSB + cq * 16;
            cp_async16(d, g);
        }
        CP_COMMIT();
    };

    float acc[2][8][4];
#pragma unroll
    for (int a = 0; a < 2; a++)
#pragma unroll
        for (int b = 0; b < 8; b++)
#pragma unroll
            for (int q = 0; q < 4; q++) acc[a][b][q] = 0.f;

    // prologue: stages 0, 1
    load_stage(0, 0);
    load_stage(1, BKC);

    // fragment address offsets (within a tile)
    const int a_row = wm * 32 + (lane & 7) + ((lane >> 3) & 1) * 8;
    const int a_kof = (lane >> 4) * 8;
    const int b_row = wn * 64 + ((lane >> 4) * 8) + (lane & 7);
    const int b_kof = ((lane >> 3) & 1) * 8;

    int cur = 0, nxt = 2;                       // stage indices mod 3
    for (int ch = 0; ch < NCHUNK; ch++) {
        if (ch + 1 < NCHUNK) { CP_WAIT(NSTAGE - 2); } else { CP_WAIT(0); }
        __syncthreads();                        // everyone's done + buf free
        if (ch + 2 < NCHUNK) {
            load_stage(nxt, (ch + 2) * BKC);    // safe: old readers finished
        }

        const uint32_t st  = sbase + cur * STAGE_SB;
        const uint32_t t_a = st;
        const uint32_t t_b = st + TILE_SB;

#pragma unroll
        for (int ks = 0; ks < 4; ks++) {
            const int kq = ks * 16;
            uint32_t aa[2][4], bb[4][4];

#pragma unroll
            for (int mi = 0; mi < 2; mi++) {
                uint32_t ad = t_a + (a_row + mi * 16) * RSB + (kq + a_kof) * 2;
                LDSM_X4(aa[mi][0], aa[mi][1], aa[mi][2], aa[mi][3], ad);
            }
#pragma unroll
            for (int ni = 0; ni < 4; ni++) {
                uint32_t bd = t_b + (b_row + ni * 16) * RSB + (kq + b_kof) * 2;
                LDSM_X4(bb[ni][0], bb[ni][1], bb[ni][2], bb[ni][3], bd);
            }
#pragma unroll
            for (int mi = 0; mi < 2; mi++)
#pragma unroll
                for (int ni = 0; ni < 4; ni++) {
                    MMA16816(acc[mi][2 * ni],     aa[mi], bb[ni][0], bb[ni][1]);
                    MMA16816(acc[mi][2 * ni + 1], aa[mi], bb[ni][2], bb[ni][3]);
                }
        }
        cur = (cur + 1 == NSTAGE) ? 0 : cur + 1;
        nxt = (nxt + 1 == NSTAGE) ? 0 : nxt + 1;
    }

    // epilogue
#pragma unroll
    for (int mi = 0; mi < 2; mi++) {
#pragma unroll
        for (int h2 = 0; h2 < 2; h2++) {
            int row = bm + wm * 32 + mi * 16 + (lane >> 2) + h2 * 8;
#pragma unroll
            for (int ng = 0; ng < 8; ng++) {
                int col = bn + wn * 64 + ng * 8 + (lane & 3) * 2;
                float x0 = acc[mi][ng][h2 * 2];
                float x1 = acc[mi][ng][h2 * 2 + 1];
                if (EPI == 1) {
                    if (bn < DIM) {
                        // x_conv path: bias + SiLU -> fp16
                        x0 += bias[col];
                        x1 += bias[col + 1];
                        x0 = x0 / (1.f + __expf(-x0));
                        x1 = x1 / (1.f + __expf(-x1));
                        __half2 hv = {__float2half(x0), __float2half(x1)};
                        *(__half2*)(Cx + (size_t)row * DIM + col) = hv;
                    } else {
                        float2 v = {x0, x1};
                        *(float2*)(C + (size_t)row * DIM + (col - DIM)) = v;
                    }
                } else {
                    float2 v = {x0, x1};
                    *(float2*)(C + (size_t)row * DIM + col) = v;
                }
            }
        }
    }
}

// ---------------- gate pre-activations (weights cached in smem) --------------
__device__ __forceinline__ float warp_sum(float v) {
#pragma unroll
    for (int o = 16; o; o >>= 1) v += __shfl_xor_sync(0xffffffffu, v, o);
    return v;
}

__device__ __forceinline__ float softcap(float x) {
    return CAP_ * tanhf(x * (1.0f / CAP_));
}

#define PRE_ROWS 32
#define PRE_SMEM ((3 * NH * DIM + 2 * DIM) * 4)   // 106496 B

__global__ __launch_bounds__(256)
void preact_kernel(const float* __restrict__ inputs,
                   const float* __restrict__ i_w, const float* __restrict__ i_b,
                   const float* __restrict__ f_w, const float* __restrict__ f_b,
                   const float* __restrict__ o_w, const float* __restrict__ o_b) {
    extern __shared__ __align__(16) float sw[];
    float* s_iw = sw;                     // [NH*DIM]
    float* s_fw = s_iw + NH * DIM;
    float* s_ow = s_fw + NH * DIM;
    float* s_xc = s_ow + NH * DIM;        // [DIM]
    float* s_xi = s_xc + DIM;             // [DIM]

    const int tid = threadIdx.x;
    const int h = tid >> 5;
    const int lane = tid & 31;

    // cache all gate weights (96 KB) once per block
#pragma unroll
    for (int i = 0; i < 8; i++) {
        int idx = tid + i * 256;          // over NH*DIM/4 = 2048 float4
        ((float4*)s_iw)[idx] = ((const float4*)i_w)[idx];
        ((float4*)s_fw)[idx] = ((const float4*)f_w)[idx];
        ((float4*)s_ow)[idx] = ((const float4*)o_w)[idx];
    }
    __syncthreads();

    const float ib = i_b[h], fb = f_b[h], ob = o_b[h];
    const int row0 = blockIdx.x * PRE_ROWS;

    for (int r = 0; r < PRE_ROWS; r++) {
        const int row = row0 + r;
        // cooperative loads: xconv fp16 (converted to fp32 smem), inputs fp32
        {
            int idx = tid;                // 256 threads
            uint2 hx = ((const uint2*)(g_xconv + (size_t)row * DIM))[idx];
            __half2 h0 = *(__half2*)&hx.x;
            __half2 h1 = *(__half2*)&hx.y;
            float2 f0 = __half22float2(h0);
            float2 f1 = __half22float2(h1);
            float4 xf = {f0.x, f0.y, f1.x, f1.y};
            ((float4*)s_xc)[idx] = xf;
            ((float4*)s_xi)[idx] = ((const float4*)(inputs + (size_t)row * DIM))[idx];
        }
        __syncthreads();

        float di = 0.f, df = 0.f, dq = 0.f;
        const float4* xc4 = (const float4*)s_xc;
        const float4* xi4 = (const float4*)s_xi;
        const float4* iw4 = (const float4*)(s_iw + h * DIM);
        const float4* fw4 = (const float4*)(s_fw + h * DIM);
        const float4* ow4 = (const float4*)(s_ow + h * DIM);
#pragma unroll
        for (int kk = 0; kk < 8; kk++) {
            int k4 = kk * 32 + lane;
            float4 xc = xc4[k4], xi = xi4[k4];
            float4 iw = iw4[k4], fw = fw4[k4], ow = ow4[k4];
            di = fmaf(xc.x, iw.x, di); di = fmaf(xc.y, iw.y, di);
            di = fmaf(xc.z, iw.z, di); di = fmaf(xc.w, iw.w, di);
            df = fmaf(xc.x, fw.x, df); df = fmaf(xc.y, fw.y, df);
            df = fmaf(xc.z, fw.z, df); df = fmaf(xc.w, fw.w, df);
            dq = fmaf(xi.x, ow.x, dq); dq = fmaf(xi.y, ow.y, dq);
            dq = fmaf(xi.z, ow.z, dq); dq = fmaf(xi.w, ow.w, dq);
        }
        di = warp_sum(di);
        df = warp_sum(df);
        dq = warp_sum(dq);
        if (lane == 0) {
            size_t p = ((size_t)row * NH + h) * 3;
            g_pre[p + 0] = softcap(di + ib);
            g_pre[p + 1] = softcap(df + fb);
            g_pre[p + 2] = dq + ob;
        }
        __syncthreads();
    }
}

// ---------------- elementwise gating + per-head layernorm --------------------
__global__ __launch_bounds__(256)
void gate_kernel(const float* __restrict__ c, const float* __restrict__ n,
                 const float* __restrict__ m,
                 const float* __restrict__ gn_w, const float* __restrict__ gn_b,
                 float* __restrict__ out_c, float* __restrict__ out_n,
                 float* __restrict__ out_m) {
    const int b = blockIdx.x;
    const int tid = threadIdx.x;
    const int h = tid >> 5;          // warp == head (NH==8 warps)
    const int lane = tid & 31;

    const size_t p = ((size_t)b * NH + h) * 3;
    const float i_t = g_pre[p + 0];
    const float f_t = g_pre[p + 1];
    const float o_t = g_pre[p + 2];

    float f_log = -log1pf(expf(-f_t));       // log(sigmoid(f_t))
    float mm    = m[(size_t)b * NH + h];
    float m_new = fmaxf(f_log + mm, i_t);
    float i_g   = expf(i_t - m_new);
    float f_g   = expf(f_log + mm - m_new);
    float o_g   = 1.f / (1.f + expf(-o_t));

    const size_t base = (size_t)b * HID + h * HDIM;
    const int e = lane * 4;                  // 4 contiguous elements per lane

    float4 cv = *(const float4*)(c + base + e);
    float4 nv = *(const float4*)(n + base + e);
    float4 zv = *(const float4*)(g_z + base + e);

    float4 cn, nn, hv;
    cn.x = fmaf(f_g, cv.x, i_g * zv.x); nn.x = fmaf(f_g, nv.x, i_g);
    cn.y = fmaf(f_g, cv.y, i_g * zv.y); nn.y = fmaf(f_g, nv.y, i_g);
    cn.z = fmaf(f_g, cv.z, i_g * zv.z); nn.z = fmaf(f_g, nv.z, i_g);
    cn.w = fmaf(f_g, cv.w, i_g * zv.w); nn.w = fmaf(f_g, nv.w, i_g);
    *(float4*)(out_c + base + e) = cn;
    *(float4*)(out_n + base + e) = nn;

    hv.x = o_g * cn.x / (nn.x + EPS_);
    hv.y = o_g * cn.y / (nn.y + EPS_);
    hv.z = o_g * cn.z / (nn.z + EPS_);
    hv.w = o_g * cn.w / (nn.w + EPS_);

    float sum   = hv.x + hv.y + hv.z + hv.w;
    float sumsq = fmaf(hv.x, hv.x, fmaf(hv.y, hv.y, fmaf(hv.z, hv.z, hv.w * hv.w)));
    sum   = warp_sum(sum);
    sumsq = warp_sum(sumsq);
    float mu   = sum * (1.0f / HDIM);
    float var  = sumsq * (1.0f / HDIM) - mu * mu;
    float rstd = rsqrtf(var + EPS_);

    float4 gw = *(const float4*)(gn_w + h * HDIM + e);
    float4 gb = *(const float4*)(gn_b + h * HDIM + e);
    float h0 = (hv.x - mu) * rstd * gw.x + gb.x;
    float h1 = (hv.y - mu) * rstd * gw.y + gb.y;
    float h2 = (hv.z - mu) * rstd * gw.z + gb.z;
    float h3 = (hv.w - mu) * rstd * gw.w + gb.w;
    __half2 p0 = {__float2half(h0), __float2half(h1)};
    __half2 p1 = {__float2half(h2), __float2half(h3)};
    uint2 hp = {*(uint32_t*)&p0, *(uint32_t*)&p1};
    *(uint2*)(g_hn + base + e) = hp;

    if (lane == 0) out_m[(size_t)b * NH + h] = m_new;
}

// ---------------- launch ------------------------------------------------------
extern "C" void kernel_launch(void* const* d_in, const int* in_sizes, int n_in,
                              void* d_out, int out_size) {
    const float* inputs = (const float*)d_in[0];
    const float* c      = (const float*)d_in[1];
    const float* n      = (const float*)d_in[2];
    const float* m      = (const float*)d_in[3];
    const float* conv_w = (const float*)d_in[4];
    const float* conv_b = (const float*)d_in[5];
    const float* z_w    = (const float*)d_in[6];
    const float* i_w    = (const float*)d_in[7];
    const float* i_b    = (const float*)d_in[8];
    const float* f_w    = (const float*)d_in[9];
    const float* f_b    = (const float*)d_in[10];
    const float* o_w    = (const float*)d_in[11];
    const float* o_b    = (const float*)d_in[12];
    const float* gn_w   = (const float*)d_in[13];
    const float* gn_b   = (const float*)d_in[14];
    const float* out_w  = (const float*)d_in[15];

    float* out   = (float*)d_out;                       // [B, D]
    float* out_c = out   + (size_t)BATCH * DIM;         // [B, NH, H]
    float* out_n = out_c + (size_t)BATCH * DIM;         // [B, NH, H]
    float* out_m = out_n + (size_t)BATCH * DIM;         // [B, NH]

    float *z_p;
    __half *xconv_p, *in_p, *hn_p, *wz_p, *ow_p;
    cudaGetSymbolAddress((void**)&xconv_p, g_xconv);
    cudaGetSymbolAddress((void**)&z_p, g_z);
    cudaGetSymbolAddress((void**)&in_p, g_in);
    cudaGetSymbolAddress((void**)&hn_p, g_hn);
    cudaGetSymbolAddress((void**)&wz_p, g_wz);
    cudaGetSymbolAddress((void**)&ow_p, g_ow);

    cudaFuncSetAttribute(mma_gemm<0>, cudaFuncAttributeMaxDynamicSharedMemorySize, GEMM_SMEM);
    cudaFuncSetAttribute(mma_gemm<1>, cudaFuncAttributeMaxDynamicSharedMemorySize, GEMM_SMEM);
    cudaFuncSetAttribute(preact_kernel, cudaFuncAttributeMaxDynamicSharedMemorySize, PRE_SMEM);

    // conversions
    {
        int n4 = (BATCH * DIM) / 4;
        cvt_h_kernel<<<n4 / 256, 256>>>(inputs, in_p, n4);
    }
    pack_w1_kernel<<<(DIM * DIM + 255) / 256, 256>>>(conv_w);
    {
        int n4 = (DIM * DIM) / 4;
        cvt_h_kernel<<<n4 / 256, 256>>>(z_w, wz_p + (size_t)DIM * DIM, n4);
        cvt_h_kernel<<<n4 / 256, 256>>>(out_w, ow_p, n4);
    }

    // fused input GEMM: [x_conv | z] = inputs @ [w1 | z_w]^T   (N = 2048)
    {
        dim3 g(2 * DIM / 128, BATCH / 128);   // (16, 256)
        mma_gemm<1><<<g, 256, GEMM_SMEM>>>(in_p, wz_p, conv_b, z_p, xconv_p);
    }
    // gate pre-activations (i_t, f_t, o_t)
    preact_kernel<<<BATCH / PRE_ROWS, 256, PRE_SMEM>>>(inputs, i_w, i_b, f_w, f_b, o_w, o_b);
    // elementwise gating + LN (emits h_norm as fp16)
    gate_kernel<<<BATCH, 256>>>(c, n, m, gn_w, gn_b, out_c, out_n, out_m);
    // out = h_norm @ out_w^T
    {
        dim3 g(DIM / 128, BATCH / 128);       // (8, 256)
        mma_gemm<0><<<g, 256, GEMM_SMEM>>>(hn_p, ow_p, nullptr, out, nullptr);
    }
}

// round 14
// speedup vs baseline: 1.1791x; 1.0006x over previous
#include <cuda_runtime.h>
#include <cuda_fp16.h>
#include <cstdint>

// Problem constants (fixed shapes)
#define BATCH 32768
#define DIM   1024
#define NH    8
#define HDIM  128
#define HID   1024
#define KCONV 4
#define EPS_  1e-6f
#define CAP_  15.0f

// ---------------- scratch (static device globals; no allocation) -------------
__device__ __half g_xconv[(size_t)BATCH * DIM];  // SiLU(conv gemm), fp16
__device__ __half g_zh[(size_t)BATCH * DIM];     // z projection, fp16
__device__ float g_pre[(size_t)BATCH * NH * 3];  // i_t, f_t, o_t per (b,h)
__device__ __half g_in[(size_t)BATCH * DIM];     // inputs, fp16
__device__ __half g_hn[(size_t)BATCH * DIM];     // h_norm, fp16
__device__ __half g_wz[(size_t)2 * DIM * DIM];   // [w1 | z_w] packed, fp16
__device__ __half g_ow[(size_t)DIM * DIM];

// ---------------- helpers -----------------------------------------------------
__device__ __forceinline__ uint32_t smem_u32(const void* p) {
    uint32_t a;
    asm("{ .reg .u64 t; cvta.to.shared.u64 t, %1; cvt.u32.u64 %0, t; }"
        : "=r"(a) : "l"(p));
    return a;
}

__device__ __forceinline__ void cp_async16(uint32_t dst, const void* src) {
    asm volatile("cp.async.cg.shared.global [%0], [%1], 16;"
                 :: "r"(dst), "l"(src) : "memory");
}
#define CP_COMMIT() asm volatile("cp.async.commit_group;" ::: "memory")
#define CP_WAIT(N)  asm volatile("cp.async.wait_group %0;" :: "n"(N) : "memory")

#define LDSM_X4(r0, r1, r2, r3, addr) \
    asm volatile("ldmatrix.sync.aligned.m8n8.x4.shared.b16 {%0,%1,%2,%3}, [%4];" \
                 : "=r"(r0), "=r"(r1), "=r"(r2), "=r"(r3) : "r"(addr))

#define MMA16816(d, a, b0v, b1v) \
    asm volatile("mma.sync.aligned.m16n8k16.row.col.f32.f16.f16.f32 " \
                 "{%0,%1,%2,%3}, {%4,%5,%6,%7}, {%8,%9}, {%0,%1,%2,%3};" \
                 : "+f"((d)[0]), "+f"((d)[1]), "+f"((d)[2]), "+f"((d)[3]) \
                 : "r"((a)[0]), "r"((a)[1]), "r"((a)[2]), "r"((a)[3]), \
                   "r"(b0v), "r"(b1v))

// ---------------- conversion kernels -----------------------------------------
// fp32 -> fp16
__global__ __launch_bounds__(256)
void cvt_h_kernel(const float* __restrict__ src, __half* __restrict__ dst, int n4) {
    int i = blockIdx.x * blockDim.x + threadIdx.x;
    if (i >= n4) return;
    float4 v = ((const float4*)src)[i];
    __half2 a = {__float2half(v.x), __float2half(v.y)};
    __half2 b = {__float2half(v.z), __float2half(v.w)};
    uint2 p = {*(uint32_t*)&a, *(uint32_t*)&b};
    ((uint2*)dst)[i] = p;
}

// pack conv tap K-1 -> fp16 (into first half of g_wz)
__global__ __launch_bounds__(256)
void pack_w1_kernel(const float* __restrict__ conv_w) {
    int idx = blockIdx.x * blockDim.x + threadIdx.x;
    if (idx < DIM * DIM)
        g_wz[idx] = __float2half(conv_w[(size_t)idx * KCONV + (KCONV - 1)]);
}

// ---------------- fp16 MMA GEMM: C[m][n] = sum_k A[m][k]*W[n][k] -------------
// CTA tile 128x128, BK=64, 256 threads (warps 4x2, each 32x64).
// 3-stage cp.async pipeline, one __syncthreads per chunk.
#define GK      1024
#define BKC     64
#define NCHUNK  (GK / BKC)          // 16
#define NSTAGE  3
#define RSB     144                 // padded smem row stride (128B data + 16B pad)
#define TILE_SB (128 * RSB)         // 18432 B per tile
#define STAGE_SB (2 * TILE_SB)      // A, B = 36864 B
#define GEMM_SMEM (NSTAGE * STAGE_SB) // 110592 B

// EPI: 0 = plain fp32 C store (out GEMM, N=1024)
//      1 = fused input GEMM (N=2048): bn<1024 -> bias+SiLU -> half to Cx;
//                                     bn>=1024 -> half to Cz
template <int EPI>
__global__ __launch_bounds__(256, 2)
void mma_gemm(const __half* __restrict__ A, const __half* __restrict__ B,
              const float* __restrict__ bias, float* __restrict__ C,
              __half* __restrict__ Cx, __half* __restrict__ Cz) {
    extern __shared__ __align__(128) char dsm[];

    const int tid  = threadIdx.x;
    const int wid  = tid >> 5;
    const int lane = tid & 31;
    const int wm   = wid & 3;      // 0..3 -> row block of 32
    const int wn   = wid >> 2;     // 0..1 -> col block of 64
    const int bm = blockIdx.y * 128;
    const int bn = blockIdx.x * 128;

    const uint32_t sbase = smem_u32(dsm);

    const __half* srcA = A + (size_t)bm * GK;
    const __half* srcB = B + (size_t)bn * GK;

    // stage loader: 2 tiles of 128 rows x 64 fp16 (128B); 16B per cp.async
    auto load_stage = [&](int stage, int k0) {
#pragma unroll
        for (int i = 0; i < 8; i++) {
            int id = tid + i * 256;        // 0..2047
            int t  = id >> 10;             // tile (0=A, 1=B)
            int r  = (id >> 3) & 127;      // row
            int cq = id & 7;               // 16B chunk in row
            const __half* s = (t == 0) ? srcA : srcB;
            const void* g = s + (size_t)r * GK + k0 + cq * 8;
            uint32_t d = sbase + stage * STAGE_SB + t * TILE_SB + r * RSB + cq * 16;
            cp_async16(d, g);
        }
        CP_COMMIT();
    };

    float acc[2][8][4];
#pragma unroll
    for (int a = 0; a < 2; a++)
#pragma unroll
        for (int b = 0; b < 8; b++)
#pragma unroll
            for (int q = 0; q < 4; q++) acc[a][b][q] = 0.f;

    // prologue: stages 0, 1
    load_stage(0, 0);
    load_stage(1, BKC);

    // fragment address offsets (within a tile)
    const int a_row = wm * 32 + (lane & 7) + ((lane >> 3) & 1) * 8;
    const int a_kof = (lane >> 4) * 8;
    const int b_row = wn * 64 + ((lane >> 4) * 8) + (lane & 7);
    const int b_kof = ((lane >> 3) & 1) * 8;

    int cur = 0, nxt = 2;                       // stage indices mod 3
    for (int ch = 0; ch < NCHUNK; ch++) {
        if (ch + 1 < NCHUNK) { CP_WAIT(NSTAGE - 2); } else { CP_WAIT(0); }
        __syncthreads();                        // everyone's done + buf free
        if (ch + 2 < NCHUNK) {
            load_stage(nxt, (ch + 2) * BKC);    // safe: old readers finished
        }

        const uint32_t st  = sbase + cur * STAGE_SB;
        const uint32_t t_a = st;
        const uint32_t t_b = st + TILE_SB;

#pragma unroll
        for (int ks = 0; ks < 4; ks++) {
            const int kq = ks * 16;
            uint32_t aa[2][4], bb[4][4];

#pragma unroll
            for (int mi = 0; mi < 2; mi++) {
                uint32_t ad = t_a + (a_row + mi * 16) * RSB + (kq + a_kof) * 2;
                LDSM_X4(aa[mi][0], aa[mi][1], aa[mi][2], aa[mi][3], ad);
            }
#pragma unroll
            for (int ni = 0; ni < 4; ni++) {
                uint32_t bd = t_b + (b_row + ni * 16) * RSB + (kq + b_kof) * 2;
                LDSM_X4(bb[ni][0], bb[ni][1], bb[ni][2], bb[ni][3], bd);
            }
#pragma unroll
            for (int mi = 0; mi < 2; mi++)
#pragma unroll
                for (int ni = 0; ni < 4; ni++) {
                    MMA16816(acc[mi][2 * ni],     aa[mi], bb[ni][0], bb[ni][1]);
                    MMA16816(acc[mi][2 * ni + 1], aa[mi], bb[ni][2], bb[ni][3]);
                }
        }
        cur = (cur + 1 == NSTAGE) ? 0 : cur + 1;
        nxt = (nxt + 1 == NSTAGE) ? 0 : nxt + 1;
    }

    // epilogue
#pragma unroll
    for (int mi = 0; mi < 2; mi++) {
#pragma unroll
        for (int h2 = 0; h2 < 2; h2++) {
            int row = bm + wm * 32 + mi * 16 + (lane >> 2) + h2 * 8;
#pragma unroll
            for (int ng = 0; ng < 8; ng++) {
                int col = bn + wn * 64 + ng * 8 + (lane & 3) * 2;
                float x0 = acc[mi][ng][h2 * 2];
                float x1 = acc[mi][ng][h2 * 2 + 1];
                if (EPI == 1) {
                    if (bn < DIM) {
                        // x_conv path: bias + SiLU -> fp16
                        x0 += bias[col];
                        x1 += bias[col + 1];
                        x0 = x0 / (1.f + __expf(-x0));
                        x1 = x1 / (1.f + __expf(-x1));
                        __half2 hv = {__float2half(x0), __float2half(x1)};
                        *(__half2*)(Cx + (size_t)row * DIM + col) = hv;
                    } else {
                        // z path -> fp16
                        __half2 hv = {__float2half(x0), __float2half(x1)};
                        *(__half2*)(Cz + (size_t)row * DIM + (col - DIM)) = hv;
                    }
                } else {
                    float2 v = {x0, x1};
                    *(float2*)(C + (size_t)row * DIM + col) = v;
                }
            }
        }
    }
}

// ---------------- gate pre-activations (weights cached in smem) --------------
__device__ __forceinline__ float warp_sum(float v) {
#pragma unroll
    for (int o = 16; o; o >>= 1) v += __shfl_xor_sync(0xffffffffu, v, o);
    return v;
}

__device__ __forceinline__ float softcap(float x) {
    return CAP_ * tanhf(x * (1.0f / CAP_));
}

#define PRE_ROWS 32
#define PRE_SMEM ((3 * NH * DIM + 2 * DIM) * 4)   // 106496 B

__global__ __launch_bounds__(256)
void preact_kernel(const float* __restrict__ i_w, const float* __restrict__ i_b,
                   const float* __restrict__ f_w, const float* __restrict__ f_b,
                   const float* __restrict__ o_w, const float* __restrict__ o_b) {
    extern __shared__ __align__(16) float sw[];
    float* s_iw = sw;                     // [NH*DIM]
    float* s_fw = s_iw + NH * DIM;
    float* s_ow = s_fw + NH * DIM;
    float* s_xc = s_ow + NH * DIM;        // [DIM]
    float* s_xi = s_xc + DIM;             // [DIM]

    const int tid = threadIdx.x;
    const int h = tid >> 5;
    const int lane = tid & 31;

    // cache all gate weights (96 KB) once per block
#pragma unroll
    for (int i = 0; i < 8; i++) {
        int idx = tid + i * 256;          // over NH*DIM/4 = 2048 float4
        ((float4*)s_iw)[idx] = ((const float4*)i_w)[idx];
        ((float4*)s_fw)[idx] = ((const float4*)f_w)[idx];
        ((float4*)s_ow)[idx] = ((const float4*)o_w)[idx];
    }
    __syncthreads();

    const float ib = i_b[h], fb = f_b[h], ob = o_b[h];
    const int row0 = blockIdx.x * PRE_ROWS;

    for (int r = 0; r < PRE_ROWS; r++) {
        const int row = row0 + r;
        // cooperative loads: xconv + inputs, both fp16 -> fp32 smem
        {
            int idx = tid;                // 256 threads, 4 elems each
            uint2 hx = ((const uint2*)(g_xconv + (size_t)row * DIM))[idx];
            __half2 c0 = *(__half2*)&hx.x;
            __half2 c1 = *(__half2*)&hx.y;
            float2 f0 = __half22float2(c0);
            float2 f1 = __half22float2(c1);
            float4 xf = {f0.x, f0.y, f1.x, f1.y};
            ((float4*)s_xc)[idx] = xf;

            uint2 hi = ((const uint2*)(g_in + (size_t)row * DIM))[idx];
            __half2 i0 = *(__half2*)&hi.x;
            __half2 i1 = *(__half2*)&hi.y;
            float2 g0 = __half22float2(i0);
            float2 g1 = __half22float2(i1);
            float4 gf = {g0.x, g0.y, g1.x, g1.y};
            ((float4*)s_xi)[idx] = gf;
        }
        __syncthreads();

        float di = 0.f, df = 0.f, dq = 0.f;
        const float4* xc4 = (const float4*)s_xc;
        const float4* xi4 = (const float4*)s_xi;
        const float4* iw4 = (const float4*)(s_iw + h * DIM);
        const float4* fw4 = (const float4*)(s_fw + h * DIM);
        const float4* ow4 = (const float4*)(s_ow + h * DIM);
#pragma unroll
        for (int kk = 0; kk < 8; kk++) {
            int k4 = kk * 32 + lane;
            float4 xc = xc4[k4], xi = xi4[k4];
            float4 iw = iw4[k4], fw = fw4[k4], ow = ow4[k4];
            di = fmaf(xc.x, iw.x, di); di = fmaf(xc.y, iw.y, di);
            di = fmaf(xc.z, iw.z, di); di = fmaf(xc.w, iw.w, di);
            df = fmaf(xc.x, fw.x, df); df = fmaf(xc.y, fw.y, df);
            df = fmaf(xc.z, fw.z, df); df = fmaf(xc.w, fw.w, df);
            dq = fmaf(xi.x, ow.x, dq); dq = fmaf(xi.y, ow.y, dq);
            dq = fmaf(xi.z, ow.z, dq); dq = fmaf(xi.w, ow.w, dq);
        }
        di = warp_sum(di);
        df = warp_sum(df);
        dq = warp_sum(dq);
        if (lane == 0) {
            size_t p = ((size_t)row * NH + h) * 3;
            g_pre[p + 0] = softcap(di + ib);
            g_pre[p + 1] = softcap(df + fb);
            g_pre[p + 2] = dq + ob;
        }
        __syncthreads();
    }
}

// ---------------- elementwise gating + per-head layernorm --------------------
__global__ __launch_bounds__(256)
void gate_kernel(const float* __restrict__ c, const float* __restrict__ n,
                 const float* __restrict__ m,
                 const float* __restrict__ gn_w, const float* __restrict__ gn_b,
                 float* __restrict__ out_c, float* __restrict__ out_n,
                 float* __restrict__ out_m) {
    const int b = blockIdx.x;
    const int tid = threadIdx.x;
    const int h = tid >> 5;          // warp == head (NH==8 warps)
    const int lane = tid & 31;

    const size_t p = ((size_t)b * NH + h) * 3;
    const float i_t = g_pre[p + 0];
    const float f_t = g_pre[p + 1];
    const float o_t = g_pre[p + 2];

    float f_log = -log1pf(expf(-f_t));       // log(sigmoid(f_t))
    float mm    = m[(size_t)b * NH + h];
    float m_new = fmaxf(f_log + mm, i_t);
    float i_g   = expf(i_t - m_new);
    float f_g   = expf(f_log + mm - m_new);
    float o_g   = 1.f / (1.f + expf(-o_t));

    const size_t base = (size_t)b * HID + h * HDIM;
    const int e = lane * 4;                  // 4 contiguous elements per lane

    float4 cv = *(const float4*)(c + base + e);
    float4 nv = *(const float4*)(n + base + e);
    uint2 hz = *(const uint2*)(g_zh + base + e);
    __half2 z0 = *(__half2*)&hz.x;
    __half2 z1 = *(__half2*)&hz.y;
    float2 zf0 = __half22float2(z0);
    float2 zf1 = __half22float2(z1);
    float4 zv = {zf0.x, zf0.y, zf1.x, zf1.y};

    float4 cn, nn, hv;
    cn.x = fmaf(f_g, cv.x, i_g * zv.x); nn.x = fmaf(f_g, nv.x, i_g);
    cn.y = fmaf(f_g, cv.y, i_g * zv.y); nn.y = fmaf(f_g, nv.y, i_g);
    cn.z = fmaf(f_g, cv.z, i_g * zv.z); nn.z = fmaf(f_g, nv.z, i_g);
    cn.w = fmaf(f_g, cv.w, i_g * zv.w); nn.w = fmaf(f_g, nv.w, i_g);
    *(float4*)(out_c + base + e) = cn;
    *(float4*)(out_n + base + e) = nn;

    hv.x = o_g * cn.x / (nn.x + EPS_);
    hv.y = o_g * cn.y / (nn.y + EPS_);
    hv.z = o_g * cn.z / (nn.z + EPS_);
    hv.w = o_g * cn.w / (nn.w + EPS_);

    float sum   = hv.x + hv.y + hv.z + hv.w;
    float sumsq = fmaf(hv.x, hv.x, fmaf(hv.y, hv.y, fmaf(hv.z, hv.z, hv.w * hv.w)));
    sum   = warp_sum(sum);
    sumsq = warp_sum(sumsq);
    float mu   = sum * (1.0f / HDIM);
    float var  = sumsq * (1.0f / HDIM) - mu * mu;
    float rstd = rsqrtf(var + EPS_);

    float4 gw = *(const float4*)(gn_w + h * HDIM + e);
    float4 gb = *(const float4*)(gn_b + h * HDIM + e);
    float h0 = (hv.x - mu) * rstd * gw.x + gb.x;
    float h1 = (hv.y - mu) * rstd * gw.y + gb.y;
    float h2 = (hv.z - mu) * rstd * gw.z + gb.z;
    float h3 = (hv.w - mu) * rstd * gw.w + gb.w;
    __half2 p0 = {__float2half(h0), __float2half(h1)};
    __half2 p1 = {__float2half(h2), __float2half(h3)};
    uint2 hp = {*(uint32_t*)&p0, *(uint32_t*)&p1};
    *(uint2*)(g_hn + base + e) = hp;

    if (lane == 0) out_m[(size_t)b * NH + h] = m_new;
}

// ---------------- launch ------------------------------------------------------
extern "C" void kernel_launch(void* const* d_in, const int* in_sizes, int n_in,
                              void* d_out, int out_size) {
    const float* inputs = (const float*)d_in[0];
    const float* c      = (const float*)d_in[1];
    const float* n      = (const float*)d_in[2];
    const float* m      = (const float*)d_in[3];
    const float* conv_w = (const float*)d_in[4];
    const float* conv_b = (const float*)d_in[5];
    const float* z_w    = (const float*)d_in[6];
    const float* i_w    = (const float*)d_in[7];
    const float* i_b    = (const float*)d_in[8];
    const float* f_w    = (const float*)d_in[9];
    const float* f_b    = (const float*)d_in[10];
    const float* o_w    = (const float*)d_in[11];
    const float* o_b    = (const float*)d_in[12];
    const float* gn_w   = (const float*)d_in[13];
    const float* gn_b   = (const float*)d_in[14];
    const float* out_w  = (const float*)d_in[15];

    float* out   = (float*)d_out;                       // [B, D]
    float* out_c = out   + (size_t)BATCH * DIM;         // [B, NH, H]
    float* out_n = out_c + (size_t)BATCH * DIM;         // [B, NH, H]
    float* out_m = out_n + (size_t)BATCH * DIM;         // [B, NH]

    __half *xconv_p, *zh_p, *in_p, *hn_p, *wz_p, *ow_p;
    cudaGetSymbolAddress((void**)&xconv_p, g_xconv);
    cudaGetSymbolAddress((void**)&zh_p, g_zh);
    cudaGetSymbolAddress((void**)&in_p, g_in);
    cudaGetSymbolAddress((void**)&hn_p, g_hn);
    cudaGetSymbolAddress((void**)&wz_p, g_wz);
    cudaGetSymbolAddress((void**)&ow_p, g_ow);

    cudaFuncSetAttribute(mma_gemm<0>, cudaFuncAttributeMaxDynamicSharedMemorySize, GEMM_SMEM);
    cudaFuncSetAttribute(mma_gemm<1>, cudaFuncAttributeMaxDynamicSharedMemorySize, GEMM_SMEM);
    cudaFuncSetAttribute(preact_kernel, cudaFuncAttributeMaxDynamicSharedMemorySize, PRE_SMEM);

    // conversions
    {
        int n4 = (BATCH * DIM) / 4;
        cvt_h_kernel<<<n4 / 256, 256>>>(inputs, in_p, n4);
    }
    pack_w1_kernel<<<(DIM * DIM + 255) / 256, 256>>>(conv_w);
    {
        int n4 = (DIM * DIM) / 4;
        cvt_h_kernel<<<n4 / 256, 256>>>(z_w, wz_p + (size_t)DIM * DIM, n4);
        cvt_h_kernel<<<n4 / 256, 256>>>(out_w, ow_p, n4);
    }

    // fused input GEMM: [x_conv | z] = inputs @ [w1 | z_w]^T   (N = 2048)
    {
        dim3 g(2 * DIM / 128, BATCH / 128);   // (16, 256)
        mma_gemm<1><<<g, 256, GEMM_SMEM>>>(in_p, wz_p, conv_b, nullptr, xconv_p, zh_p);
    }
    // gate pre-activations (i_t, f_t, o_t)
    preact_kernel<<<BATCH / PRE_ROWS, 256, PRE_SMEM>>>(i_w, i_b, f_w, f_b, o_w, o_b);
    // elementwise gating + LN (emits h_norm as fp16)
    gate_kernel<<<BATCH, 256>>>(c, n, m, gn_w, gn_b, out_c, out_n, out_m);
    // out = h_norm @ out_w^T
    {
        dim3 g(DIM / 128, BATCH / 128);       // (8, 256)
        mma_gemm<0><<<g, 256, GEMM_SMEM>>>(hn_p, ow_p, nullptr, out, nullptr, nullptr);
    }
}

// round 15
// speedup vs baseline: 1.5230x; 1.2916x over previous
#include <cuda_runtime.h>
#include <cuda_fp16.h>
#include <cstdint>

// Problem constants (fixed shapes)
#define BATCH 32768
#define DIM   1024
#define NH    8
#define HDIM  128
#define HID   1024
#define KCONV 4
#define EPS_  1e-6f
#define CAP_  15.0f

// ---------------- scratch (static device globals; no allocation) -------------
__device__ __half g_xconv[(size_t)BATCH * DIM];  // SiLU(conv gemm), fp16
__device__ __half g_zh[(size_t)BATCH * DIM];     // z projection, fp16
__device__ float g_pre[(size_t)BATCH * NH * 3];  // i_t, f_t, o_t per (b,h)
__device__ __half g_in[(size_t)BATCH * DIM];     // inputs, fp16
__device__ __half g_hn[(size_t)BATCH * DIM];     // h_norm, fp16
__device__ __half g_wz[(size_t)2 * DIM * DIM];   // [w1 | z_w] packed, fp16
__device__ __half g_ow[(size_t)DIM * DIM];
__device__ __half g_gw[(size_t)24 * DIM];        // [i_w(8); f_w(8); o_w(8)] fp16

// ---------------- helpers -----------------------------------------------------
__device__ __forceinline__ uint32_t smem_u32(const void* p) {
    uint32_t a;
    asm("{ .reg .u64 t; cvta.to.shared.u64 t, %1; cvt.u32.u64 %0, t; }"
        : "=r"(a) : "l"(p));
    return a;
}

__device__ __forceinline__ void cp_async16(uint32_t dst, const void* src) {
    asm volatile("cp.async.cg.shared.global [%0], [%1], 16;"
                 :: "r"(dst), "l"(src) : "memory");
}
#define CP_COMMIT() asm volatile("cp.async.commit_group;" ::: "memory")
#define CP_WAIT(N)  asm volatile("cp.async.wait_group %0;" :: "n"(N) : "memory")

#define LDSM_X4(r0, r1, r2, r3, addr) \
    asm volatile("ldmatrix.sync.aligned.m8n8.x4.shared.b16 {%0,%1,%2,%3}, [%4];" \
                 : "=r"(r0), "=r"(r1), "=r"(r2), "=r"(r3) : "r"(addr))

#define MMA16816(d, a, b0v, b1v) \
    asm volatile("mma.sync.aligned.m16n8k16.row.col.f32.f16.f16.f32 " \
                 "{%0,%1,%2,%3}, {%4,%5,%6,%7}, {%8,%9}, {%0,%1,%2,%3};" \
                 : "+f"((d)[0]), "+f"((d)[1]), "+f"((d)[2]), "+f"((d)[3]) \
                 : "r"((a)[0]), "r"((a)[1]), "r"((a)[2]), "r"((a)[3]), \
                   "r"(b0v), "r"(b1v))

// ---------------- conversion kernels -----------------------------------------
__global__ __launch_bounds__(256)
void cvt_h_kernel(const float* __restrict__ src, __half* __restrict__ dst, int n4) {
    int i = blockIdx.x * blockDim.x + threadIdx.x;
    if (i >= n4) return;
    float4 v = ((const float4*)src)[i];
    __half2 a = {__float2half(v.x), __float2half(v.y)};
    __half2 b = {__float2half(v.z), __float2half(v.w)};
    uint2 p = {*(uint32_t*)&a, *(uint32_t*)&b};
    ((uint2*)dst)[i] = p;
}

// pack conv tap K-1 -> fp16 (into first half of g_wz)
__global__ __launch_bounds__(256)
void pack_w1_kernel(const float* __restrict__ conv_w) {
    int idx = blockIdx.x * blockDim.x + threadIdx.x;
    if (idx < DIM * DIM)
        g_wz[idx] = __float2half(conv_w[(size_t)idx * KCONV + (KCONV - 1)]);
}

// pack gate weights -> g_gw fp16 (rows 0-7 i_w, 8-15 f_w, 16-23 o_w)
__global__ __launch_bounds__(256)
void pack_gw_kernel(const float* __restrict__ i_w, const float* __restrict__ f_w,
                    const float* __restrict__ o_w) {
    int idx = blockIdx.x * blockDim.x + threadIdx.x;
    if (idx >= 24 * DIM) return;
    int r = idx >> 10, cidx = idx & (DIM - 1);
    float v = (r < 8) ? i_w[r * DIM + cidx]
            : (r < 16) ? f_w[(r - 8) * DIM + cidx]
                       : o_w[(r - 16) * DIM + cidx];
    g_gw[idx] = __float2half(v);
}

// ---------------- fp16 MMA GEMM: C[m][n] = sum_k A[m][k]*W[n][k] -------------
#define GK      1024
#define BKC     64
#define NCHUNK  (GK / BKC)          // 16
#define NSTAGE  3
#define RSB     144                 // padded smem row stride (128B data + 16B pad)
#define TILE_SB (128 * RSB)         // 18432 B per tile
#define STAGE_SB (2 * TILE_SB)      // A, B = 36864 B
#define GEMM_SMEM (NSTAGE * STAGE_SB) // 110592 B

template <int EPI>
__global__ __launch_bounds__(256, 2)
void mma_gemm(const __half* __restrict__ A, const __half* __restrict__ B,
              const float* __restrict__ bias, float* __restrict__ C,
              __half* __restrict__ Cx, __half* __restrict__ Cz) {
    extern __shared__ __align__(128) char dsm[];

    const int tid  = threadIdx.x;
    const int wid  = tid >> 5;
    const int lane = tid & 31;
    const int wm   = wid & 3;
    const int wn   = wid >> 2;
    const int bm = blockIdx.y * 128;
    const int bn = blockIdx.x * 128;

    const uint32_t sbase = smem_u32(dsm);

    const __half* srcA = A + (size_t)bm * GK;
    const __half* srcB = B + (size_t)bn * GK;

    auto load_stage = [&](int stage, int k0) {
#pragma unroll
        for (int i = 0; i < 8; i++) {
            int id = tid + i * 256;
            int t  = id >> 10;
            int r  = (id >> 3) & 127;
            int cq = id & 7;
            const __half* s = (t == 0) ? srcA : srcB;
            const void* g = s + (size_t)r * GK + k0 + cq * 8;
            uint32_t d = sbase + stage * STAGE_SB + t * TILE_SB + r * RSB + cq * 16;
            cp_async16(d, g);
        }
        CP_COMMIT();
    };

    float acc[2][8][4];
#pragma unroll
    for (int a = 0; a < 2; a++)
#pragma unroll
        for (int b = 0; b < 8; b++)
#pragma unroll
            for (int q = 0; q < 4; q++) acc[a][b][q] = 0.f;

    load_stage(0, 0);
    load_stage(1, BKC);

    const int a_row = wm * 32 + (lane & 7) + ((lane >> 3) & 1) * 8;
    const int a_kof = (lane >> 4) * 8;
    const int b_row = wn * 64 + ((lane >> 4) * 8) + (lane & 7);
    const int b_kof = ((lane >> 3) & 1) * 8;

    int cur = 0, nxt = 2;
    for (int ch = 0; ch < NCHUNK; ch++) {
        if (ch + 1 < NCHUNK) { CP_WAIT(NSTAGE - 2); } else { CP_WAIT(0); }
        __syncthreads();
        if (ch + 2 < NCHUNK) {
            load_stage(nxt, (ch + 2) * BKC);
        }

        const uint32_t st  = sbase + cur * STAGE_SB;
        const uint32_t t_a = st;
        const uint32_t t_b = st + TILE_SB;

#pragma unroll
        for (int ks = 0; ks < 4; ks++) {
            const int kq = ks * 16;
            uint32_t aa[2][4], bb[4][4];

#pragma unroll
            for (int mi = 0; mi < 2; mi++) {
                uint32_t ad = t_a + (a_row + mi * 16) * RSB + (kq + a_kof) * 2;
                LDSM_X4(aa[mi][0], aa[mi][1], aa[mi][2], aa[mi][3], ad);
            }
#pragma unroll
            for (int ni = 0; ni < 4; ni++) {
                uint32_t bd = t_b + (b_row + ni * 16) * RSB + (kq + b_kof) * 2;
                LDSM_X4(bb[ni][0], bb[ni][1], bb[ni][2], bb[ni][3], bd);
            }
#pragma unroll
            for (int mi = 0; mi < 2; mi++)
#pragma unroll
                for (int ni = 0; ni < 4; ni++) {
                    MMA16816(acc[mi][2 * ni],     aa[mi], bb[ni][0], bb[ni][1]);
                    MMA16816(acc[mi][2 * ni + 1], aa[mi], bb[ni][2], bb[ni][3]);
                }
        }
        cur = (cur + 1 == NSTAGE) ? 0 : cur + 1;
        nxt = (nxt + 1 == NSTAGE) ? 0 : nxt + 1;
    }

    // epilogue
#pragma unroll
    for (int mi = 0; mi < 2; mi++) {
#pragma unroll
        for (int h2 = 0; h2 < 2; h2++) {
            int row = bm + wm * 32 + mi * 16 + (lane >> 2) + h2 * 8;
#pragma unroll
            for (int ng = 0; ng < 8; ng++) {
                int col = bn + wn * 64 + ng * 8 + (lane & 3) * 2;
                float x0 = acc[mi][ng][h2 * 2];
                float x1 = acc[mi][ng][h2 * 2 + 1];
                if (EPI == 1) {
                    if (bn < DIM) {
                        x0 += bias[col];
                        x1 += bias[col + 1];
                        x0 = x0 / (1.f + __expf(-x0));
                        x1 = x1 / (1.f + __expf(-x1));
                        __half2 hv = {__float2half(x0), __float2half(x1)};
                        *(__half2*)(Cx + (size_t)row * DIM + col) = hv;
                    } else {
                        __half2 hv = {__float2half(x0), __float2half(x1)};
                        *(__half2*)(Cz + (size_t)row * DIM + (col - DIM)) = hv;
                    }
                } else {
                    float2 v = {x0, x1};
                    *(float2*)(C + (size_t)row * DIM + col) = v;
                }
            }
        }
    }
}

// ---------------- gate pre-activations via mma (weights resident in smem) ----
__device__ __forceinline__ float warp_sum(float v) {
#pragma unroll
    for (int o = 16; o; o >>= 1) v += __shfl_xor_sync(0xffffffffu, v, o);
    return v;
}

__device__ __forceinline__ float softcap(float x) {
    return CAP_ * tanhf(x * (1.0f / CAP_));
}

#define PRE_BRS 2064                  // B row stride: 1024 fp16 + 8 pad
#define PRE_RSB 144                   // A chunk row stride
#define PRE_CH  (128 * PRE_RSB)       // 18432
#define PRE_SMEM (32 * PRE_BRS + 2 * PRE_CH)   // 66048 + 36864 = 102912

__global__ __launch_bounds__(256, 2)
void preact_mma_kernel(const float* __restrict__ i_b, const float* __restrict__ f_b,
                       const float* __restrict__ o_b) {
    extern __shared__ __align__(128) char ps[];
    const uint32_t bB = smem_u32(ps);
    const uint32_t bA = bB + 32 * PRE_BRS;
    const int tid = threadIdx.x, wid = tid >> 5, lane = tid & 31;
    const int bm = blockIdx.x * 128;

    const __half* A1 = g_xconv + (size_t)bm * DIM;   // phase 1 (i, f gates)
    const __half* A2 = g_in    + (size_t)bm * DIM;   // phase 2 (o gate)

    // load all 24 weight rows into smem B (one-time)
#pragma unroll
    for (int i = 0; i < 12; i++) {
        int id = tid + i * 256;          // 0..3071 (24 rows x 128 16B-chunks)
        int r = id >> 7, cq = id & 127;
        cp_async16(bB + r * PRE_BRS + cq * 16,
                   (const __half*)g_gw + (size_t)r * DIM + cq * 8);
    }
    CP_COMMIT();

    auto loadA = [&](int stage, int t) {
        const __half* src = (t < 16) ? A1 : A2;
        int k0 = ((t < 16) ? t : t - 16) * 64;
#pragma unroll
        for (int i = 0; i < 4; i++) {
            int id = tid + i * 256;      // 0..1023
            int r = id >> 3, cq = id & 7;
            cp_async16(bA + stage * PRE_CH + r * PRE_RSB + cq * 16,
                       src + (size_t)r * DIM + k0 + cq * 8);
        }
        CP_COMMIT();
    };

    float acc1[2][4];                    // phase 1: two n-tiles (i heads, f heads)
    float acc2[4];                       // phase 2: one n-tile (o heads)
#pragma unroll
    for (int nt = 0; nt < 2; nt++)
#pragma unroll
        for (int q = 0; q < 4; q++) acc1[nt][q] = 0.f;
#pragma unroll
    for (int q = 0; q < 4; q++) acc2[q] = 0.f;

    // fragment offsets
    const int a_row = wid * 16 + (lane & 7) + ((lane >> 3) & 1) * 8;
    const int a_kof = (lane >> 4) * 8;
    const int b_row = ((lane >> 4) * 8) + (lane & 7);
    const int b_kof = ((lane >> 3) & 1) * 8;

    loadA(0, 0);
    CP_WAIT(0);                          // B + chunk 0
    __syncthreads();

    for (int t = 0; t < 32; t++) {
        const int cur = t & 1;
        if (t > 0) { CP_WAIT(0); __syncthreads(); }
        if (t + 1 < 32) loadA(cur ^ 1, t + 1);

        const bool ph1 = (t < 16);
        const uint32_t bOff = ph1 ? 0u : (uint32_t)(16 * PRE_BRS);
        const int kbase = (ph1 ? t : t - 16) * 64;

#pragma unroll
        for (int ks = 0; ks < 4; ks++) {
            uint32_t aa[4], bb[4];
            LDSM_X4(aa[0], aa[1], aa[2], aa[3],
                    bA + cur * PRE_CH + a_row * PRE_RSB + (ks * 16 + a_kof) * 2);
            LDSM_X4(bb[0], bb[1], bb[2], bb[3],
                    bB + bOff + b_row * PRE_BRS + (kbase + ks * 16 + b_kof) * 2);
            if (ph1) {
                MMA16816(acc1[0], aa, bb[0], bb[1]);
                MMA16816(acc1[1], aa, bb[2], bb[3]);
            } else {
                MMA16816(acc2, aa, bb[0], bb[1]);
            }
        }
    }

    // epilogue: scatter to g_pre
#pragma unroll
    for (int nt = 0; nt < 2; nt++)
#pragma unroll
        for (int cc = 0; cc < 4; cc++) {
            int row = bm + wid * 16 + (lane >> 2) + (cc >> 1) * 8;
            int j = nt * 8 + (lane & 3) * 2 + (cc & 1);
            float v = acc1[nt][cc];
            if (j < 8)
                g_pre[((size_t)row * NH + j) * 3 + 0] = softcap(v + i_b[j]);
            else
                g_pre[((size_t)row * NH + (j - 8)) * 3 + 1] = softcap(v + f_b[j - 8]);
        }
#pragma unroll
    for (int cc = 0; cc < 4; cc++) {
        int row = bm + wid * 16 + (lane >> 2) + (cc >> 1) * 8;
        int h = (lane & 3) * 2 + (cc & 1);
        g_pre[((size_t)row * NH + h) * 3 + 2] = acc2[cc] + o_b[h];
    }
}

// ---------------- elementwise gating + per-head layernorm (4 rows/block) -----
#define GATE_ROWS 4

__global__ __launch_bounds__(256)
void gate_kernel(const float* __restrict__ c, const float* __restrict__ n,
                 const float* __restrict__ m,
                 const float* __restrict__ gn_w, const float* __restrict__ gn_b,
                 float* __restrict__ out_c, float* __restrict__ out_n,
                 float* __restrict__ out_m) {
    const int b0 = blockIdx.x * GATE_ROWS;
    const int tid = threadIdx.x;
    const int h = tid >> 5;          // warp == head (NH==8 warps)
    const int lane = tid & 31;
    const int e = lane * 4;

    const float4 gw = *(const float4*)(gn_w + h * HDIM + e);
    const float4 gb = *(const float4*)(gn_b + h * HDIM + e);

#pragma unroll
    for (int r = 0; r < GATE_ROWS; r++) {
        const int b = b0 + r;
        const size_t p = ((size_t)b * NH + h) * 3;
        const float i_t = g_pre[p + 0];
        const float f_t = g_pre[p + 1];
        const float o_t = g_pre[p + 2];

        float f_log = -log1pf(expf(-f_t));       // log(sigmoid(f_t))
        float mm    = m[(size_t)b * NH + h];
        float m_new = fmaxf(f_log + mm, i_t);
        float i_g   = expf(i_t - m_new);
        float f_g   = expf(f_log + mm - m_new);
        float o_g   = 1.f / (1.f + expf(-o_t));

        const size_t base = (size_t)b * HID + h * HDIM;

        float4 cv = *(const float4*)(c + base + e);
        float4 nv = *(const float4*)(n + base + e);
        uint2 hz = *(const uint2*)(g_zh + base + e);
        __half2 z0 = *(__half2*)&hz.x;
        __half2 z1 = *(__half2*)&hz.y;
        float2 zf0 = __half22float2(z0);
        float2 zf1 = __half22float2(z1);

        float4 cn, nn, hv;
        cn.x = fmaf(f_g, cv.x, i_g * zf0.x); nn.x = fmaf(f_g, nv.x, i_g);
        cn.y = fmaf(f_g, cv.y, i_g * zf0.y); nn.y = fmaf(f_g, nv.y, i_g);
        cn.z = fmaf(f_g, cv.z, i_g * zf1.x); nn.z = fmaf(f_g, nv.z, i_g);
        cn.w = fmaf(f_g, cv.w, i_g * zf1.y); nn.w = fmaf(f_g, nv.w, i_g);
        *(float4*)(out_c + base + e) = cn;
        *(float4*)(out_n + base + e) = nn;

        hv.x = o_g * cn.x / (nn.x + EPS_);
        hv.y = o_g * cn.y / (nn.y + EPS_);
        hv.z = o_g * cn.z / (nn.z + EPS_);
        hv.w = o_g * cn.w / (nn.w + EPS_);

        float sum   = hv.x + hv.y + hv.z + hv.w;
        float sumsq = fmaf(hv.x, hv.x, fmaf(hv.y, hv.y, fmaf(hv.z, hv.z, hv.w * hv.w)));
        sum   = warp_sum(sum);
        sumsq = warp_sum(sumsq);
        float mu   = sum * (1.0f / HDIM);
        float var  = sumsq * (1.0f / HDIM) - mu * mu;
        float rstd = rsqrtf(var + EPS_);

        float h0 = (hv.x - mu) * rstd * gw.x + gb.x;
        float h1 = (hv.y - mu) * rstd * gw.y + gb.y;
        float h2 = (hv.z - mu) * rstd * gw.z + gb.z;
        float h3 = (hv.w - mu) * rstd * gw.w + gb.w;
        __half2 p0 = {__float2half(h0), __float2half(h1)};
        __half2 p1 = {__float2half(h2), __float2half(h3)};
        uint2 hp = {*(uint32_t*)&p0, *(uint32_t*)&p1};
        *(uint2*)(g_hn + base + e) = hp;

        if (lane == 0) out_m[(size_t)b * NH + h] = m_new;
    }
}

// ---------------- launch ------------------------------------------------------
extern "C" void kernel_launch(void* const* d_in, const int* in_sizes, int n_in,
                              void* d_out, int out_size) {
    const float* inputs = (const float*)d_in[0];
    const float* c      = (const float*)d_in[1];
    const float* n      = (const float*)d_in[2];
    const float* m      = (const float*)d_in[3];
    const float* conv_w = (const float*)d_in[4];
    const float* conv_b = (const float*)d_in[5];
    const float* z_w    = (const float*)d_in[6];
    const float* i_w    = (const float*)d_in[7];
    const float* i_b    = (const float*)d_in[8];
    const float* f_w    = (const float*)d_in[9];
    const float* f_b    = (const float*)d_in[10];
    const float* o_w    = (const float*)d_in[11];
    const float* o_b    = (const float*)d_in[12];
    const float* gn_w   = (const float*)d_in[13];
    const float* gn_b   = (const float*)d_in[14];
    const float* out_w  = (const float*)d_in[15];

    float* out   = (float*)d_out;                       // [B, D]
    float* out_c = out   + (size_t)BATCH * DIM;         // [B, NH, H]
    float* out_n = out_c + (size_t)BATCH * DIM;         // [B, NH, H]
    float* out_m = out_n + (size_t)BATCH * DIM;         // [B, NH]

    __half *xconv_p, *zh_p, *in_p, *hn_p, *wz_p, *ow_p;
    cudaGetSymbolAddress((void**)&xconv_p, g_xconv);
    cudaGetSymbolAddress((void**)&zh_p, g_zh);
    cudaGetSymbolAddress((void**)&in_p, g_in);
    cudaGetSymbolAddress((void**)&hn_p, g_hn);
    cudaGetSymbolAddress((void**)&wz_p, g_wz);
    cudaGetSymbolAddress((void**)&ow_p, g_ow);

    cudaFuncSetAttribute(mma_gemm<0>, cudaFuncAttributeMaxDynamicSharedMemorySize, GEMM_SMEM);
    cudaFuncSetAttribute(mma_gemm<1>, cudaFuncAttributeMaxDynamicSharedMemorySize, GEMM_SMEM);
    cudaFuncSetAttribute(preact_mma_kernel, cudaFuncAttributeMaxDynamicSharedMemorySize, PRE_SMEM);

    // conversions / packing
    {
        int n4 = (BATCH * DIM) / 4;
        cvt_h_kernel<<<n4 / 256, 256>>>(inputs, in_p, n4);
    }
    pack_w1_kernel<<<(DIM * DIM + 255) / 256, 256>>>(conv_w);
    pack_gw_kernel<<<(24 * DIM + 255) / 256, 256>>>(i_w, f_w, o_w);
    {
        int n4 = (DIM * DIM) / 4;
        cvt_h_kernel<<<n4 / 256, 256>>>(z_w, wz_p + (size_t)DIM * DIM, n4);
        cvt_h_kernel<<<n4 / 256, 256>>>(out_w, ow_p, n4);
    }

    // fused input GEMM: [x_conv | z] = inputs @ [w1 | z_w]^T   (N = 2048)
    {
        dim3 g(2 * DIM / 128, BATCH / 128);   // (16, 256)
        mma_gemm<1><<<g, 256, GEMM_SMEM>>>(in_p, wz_p, conv_b, nullptr, xconv_p, zh_p);
    }
    // gate pre-activations (i_t, f_t, o_t) via mma
    preact_mma_kernel<<<BATCH / 128, 256, PRE_SMEM>>>(i_b, f_b, o_b);
    // elementwise gating + LN (emits h_norm as fp16)
    gate_kernel<<<BATCH / GATE_ROWS, 256>>>(c, n, m, gn_w, gn_b, out_c, out_n, out_m);
    // out = h_norm @ out_w^T
    {
        dim3 g(DIM / 128, BATCH / 128);       // (8, 256)
        mma_gemm<0><<<g, 256, GEMM_SMEM>>>(hn_p, ow_p, nullptr, out, nullptr, nullptr);
    }
}